// round 6
// baseline (speedup 1.0000x reference)
#include <cuda_runtime.h>
#include <cuda_bf16.h>

// B=4, N=4096, D=64, H=256.
// out[b,q,dv] = (softmax_k( -0.5*cdistL1(Ks,Qs)^2 ) @ V) * Wo
//   Ks = KEY*mlp(KEY), Qs = QUERY*mlp(QUERY), Wo = mlpo(QUERY)
// L1 dist(k,q) = sk[k] + sq[q] - 2*sum_d min(Ks,Qs); flash softmax tracks min score.

#define NB   4
#define NSEQ 4096
#define DD   64
#define NROWS (NB * NSEQ)

__device__ float g_Ks[NROWS * DD];
__device__ float g_Qs[NROWS * DD];
__device__ float g_Wo[NROWS * DD];
__device__ float g_sk[NROWS];
__device__ float g_sq[NROWS];

// ---- packed fp32x2 (Blackwell FADD2/FFMA2, only reachable via PTX) ----
__device__ __forceinline__ void addx2(float& ax, float& ay, float bx, float by) {
    asm("{\n\t.reg .b64 ra, rb;\n\t"
        "mov.b64 ra, {%0, %1};\n\t"
        "mov.b64 rb, {%2, %3};\n\t"
        "add.rn.f32x2 ra, ra, rb;\n\t"
        "mov.b64 {%0, %1}, ra;\n\t}"
        : "+f"(ax), "+f"(ay) : "f"(bx), "f"(by));
}
__device__ __forceinline__ void fmax2(float& cx, float& cy, float ax, float ay,
                                      float bx, float by) {
    asm("{\n\t.reg .b64 rc, ra, rb;\n\t"
        "mov.b64 rc, {%0, %1};\n\t"
        "mov.b64 ra, {%2, %3};\n\t"
        "mov.b64 rb, {%4, %5};\n\t"
        "fma.rn.f32x2 rc, ra, rb, rc;\n\t"
        "mov.b64 {%0, %1}, rc;\n\t}"
        : "+f"(cx), "+f"(cy) : "f"(ax), "f"(ay), "f"(bx), "f"(by));
}
__device__ __forceinline__ float dupreg(float x) {
    float y;
    asm volatile("mov.f32 %0, %1;" : "=f"(y) : "f"(x));
    return y;
}

// ---------------------------------------------------------------------------
// MLP kernel. One block = 16 rows (2 blocks/SM). mode: 0 KEY->Ks,sk ;
// 1 QUERY->Qs,sq ; 2 QUERY->Wo. Layers 64 ->256 relu -> 256 relu -> 64.
// ---------------------------------------------------------------------------
#define MLP_SMEM_FLOATS (16*68 + 16*260 + 16*260 + 64*260)

__global__ void __launch_bounds__(256, 2) mlp_kernel(
    const float* __restrict__ KEY, const float* __restrict__ QUERY,
    const float* __restrict__ W1,  const float* __restrict__ B1,
    const float* __restrict__ W2,  const float* __restrict__ B2,
    const float* __restrict__ W3,  const float* __restrict__ B3,
    const float* __restrict__ W1o, const float* __restrict__ B1o,
    const float* __restrict__ W2o, const float* __restrict__ B2o,
    const float* __restrict__ W3o, const float* __restrict__ B3o)
{
    extern __shared__ float sm[];
    float* s_x = sm;              // 16*68
    float* s_a = s_x + 16 * 68;   // 16*260
    float* s_b = s_a + 16 * 260;  // 16*260
    float* s_w = s_b + 16 * 260;  // 64*260 (transposed weight chunk [in][out])

    const int t    = threadIdx.x;
    const int mode = blockIdx.y;
    const int row0 = blockIdx.x * 16;

    const float* X  = (mode == 0) ? KEY : QUERY;
    const float* w1 = (mode < 2) ? W1 : W1o;
    const float* b1 = (mode < 2) ? B1 : B1o;
    const float* w2 = (mode < 2) ? W2 : W2o;
    const float* b2 = (mode < 2) ? B2 : B2o;
    const float* w3 = (mode < 2) ? W3 : W3o;
    const float* b3 = (mode < 2) ? B3 : B3o;

    // input tile 16x64
    for (int idx = t; idx < 16 * 16; idx += 256) {
        int r = idx >> 4, c = (idx & 15) * 4;
        *(float4*)(s_x + r * 68 + c) =
            *(const float4*)(X + (size_t)(row0 + r) * 64 + c);
    }
    // stage W1 (256x64) transposed
    for (int idx = t; idx < 256 * 64; idx += 256) {
        int o = idx >> 6, i = idx & 63;
        s_w[i * 260 + o] = w1[idx];
    }
    __syncthreads();

    const int og = t & 31;   // 32 out-groups of 8
    const int rg = t >> 5;   // 8 row-groups of 2

    // ================= Layer 1: 64 -> 256, relu -> s_a =================
    {
        float acc[2][8];
#pragma unroll
        for (int r = 0; r < 2; r++)
#pragma unroll
            for (int c = 0; c < 8; c++) acc[r][c] = 0.f;

#pragma unroll 8
        for (int i = 0; i < 64; i++) {
            float a0 = s_x[(rg * 2 + 0) * 68 + i];
            float a1 = s_x[(rg * 2 + 1) * 68 + i];
            float a0d = dupreg(a0), a1d = dupreg(a1);
            float4 wA = *(const float4*)(s_w + i * 260 + og * 8);
            float4 wB = *(const float4*)(s_w + i * 260 + og * 8 + 4);
            fmax2(acc[0][0], acc[0][1], a0, a0d, wA.x, wA.y);
            fmax2(acc[0][2], acc[0][3], a0, a0d, wA.z, wA.w);
            fmax2(acc[0][4], acc[0][5], a0, a0d, wB.x, wB.y);
            fmax2(acc[0][6], acc[0][7], a0, a0d, wB.z, wB.w);
            fmax2(acc[1][0], acc[1][1], a1, a1d, wA.x, wA.y);
            fmax2(acc[1][2], acc[1][3], a1, a1d, wA.z, wA.w);
            fmax2(acc[1][4], acc[1][5], a1, a1d, wB.x, wB.y);
            fmax2(acc[1][6], acc[1][7], a1, a1d, wB.z, wB.w);
        }
#pragma unroll
        for (int c = 0; c < 8; c++) {
            int o = og * 8 + c;
            float bv = __ldg(b1 + o);
#pragma unroll
            for (int r = 0; r < 2; r++)
                s_a[(rg * 2 + r) * 260 + o] = fmaxf(acc[r][c] + bv, 0.f);
        }
    }

    // ================= Layer 2: 256 -> 256, relu -> s_b =================
    {
        float acc[2][8];
#pragma unroll
        for (int r = 0; r < 2; r++)
#pragma unroll
            for (int c = 0; c < 8; c++) acc[r][c] = 0.f;

        for (int ch = 0; ch < 4; ch++) {
            __syncthreads();
            for (int idx = t; idx < 256 * 64; idx += 256) {
                int o = idx >> 6, i = idx & 63;
                s_w[i * 260 + o] = w2[o * 256 + ch * 64 + i];
            }
            __syncthreads();
#pragma unroll 8
            for (int i = 0; i < 64; i++) {
                float a0 = s_a[(rg * 2 + 0) * 260 + ch * 64 + i];
                float a1 = s_a[(rg * 2 + 1) * 260 + ch * 64 + i];
                float a0d = dupreg(a0), a1d = dupreg(a1);
                float4 wA = *(const float4*)(s_w + i * 260 + og * 8);
                float4 wB = *(const float4*)(s_w + i * 260 + og * 8 + 4);
                fmax2(acc[0][0], acc[0][1], a0, a0d, wA.x, wA.y);
                fmax2(acc[0][2], acc[0][3], a0, a0d, wA.z, wA.w);
                fmax2(acc[0][4], acc[0][5], a0, a0d, wB.x, wB.y);
                fmax2(acc[0][6], acc[0][7], a0, a0d, wB.z, wB.w);
                fmax2(acc[1][0], acc[1][1], a1, a1d, wA.x, wA.y);
                fmax2(acc[1][2], acc[1][3], a1, a1d, wA.z, wA.w);
                fmax2(acc[1][4], acc[1][5], a1, a1d, wB.x, wB.y);
                fmax2(acc[1][6], acc[1][7], a1, a1d, wB.z, wB.w);
            }
        }
#pragma unroll
        for (int c = 0; c < 8; c++) {
            int o = og * 8 + c;
            float bv = __ldg(b2 + o);
#pragma unroll
            for (int r = 0; r < 2; r++)
                s_b[(rg * 2 + r) * 260 + o] = fmaxf(acc[r][c] + bv, 0.f);
        }
    }

    // ================= Layer 3: 256 -> 64 + epilogue =================
    {
        const int row = t >> 4;   // 16 rows, 16 threads each
        const int o4  = t & 15;   // 16 out-groups of 4
        float acc3[4];
#pragma unroll
        for (int c = 0; c < 4; c++) acc3[c] = 0.f;

        for (int ch = 0; ch < 4; ch++) {
            __syncthreads();
            for (int idx = t; idx < 64 * 64; idx += 256) {
                int o = idx >> 6, i = idx & 63;
                s_w[i * 260 + o] = w3[o * 256 + ch * 64 + i];
            }
            __syncthreads();
#pragma unroll 8
            for (int i = 0; i < 64; i++) {
                float a = s_b[row * 260 + ch * 64 + i];
                float4 wA = *(const float4*)(s_w + i * 260 + o4 * 4);
                acc3[0] += a * wA.x; acc3[1] += a * wA.y;
                acc3[2] += a * wA.z; acc3[3] += a * wA.w;
            }
        }

        float val[4];
        float sum = 0.f;
#pragma unroll
        for (int c = 0; c < 4; c++) {
            int o = o4 * 4 + c;
            float y = acc3[c] + __ldg(b3 + o);
            if (mode < 2) { val[c] = y * s_x[row * 68 + o]; sum += val[c]; }
            else          { val[c] = y; }
        }
        float* dst = (mode == 0) ? g_Ks : (mode == 1) ? g_Qs : g_Wo;
        size_t grow = (size_t)(row0 + row);
        *(float4*)(dst + grow * 64 + o4 * 4) = make_float4(val[0], val[1], val[2], val[3]);
        if (mode < 2) {
            sum += __shfl_xor_sync(0xffffffffu, sum, 1);
            sum += __shfl_xor_sync(0xffffffffu, sum, 2);
            sum += __shfl_xor_sync(0xffffffffu, sum, 4);
            sum += __shfl_xor_sync(0xffffffffu, sum, 8);
            if (o4 == 0) ((mode == 0) ? g_sk : g_sq)[grow] = sum;
        }
    }
}

// ---------------------------------------------------------------------------
// Attention. Block = 64 queries (8 warps x 8 q), key chunks of 64.
// Lane owns 2 keys for scores, dv pair {2*lane,2*lane+1} for AV.
// p stored duplicated ({p,p,p',p'}) so one broadcast LDS.128 feeds two FFMA2.
// ---------------------------------------------------------------------------
#define ATT_SMEM_FLOATS (64*68 + 64*68 + 64*68 + 64*136 + 64)

__global__ void __launch_bounds__(256, 2) attn_kernel(
    const float* __restrict__ V, float* __restrict__ out)
{
    extern __shared__ float sm[];
    float* s_q  = sm;               // [64][68]  Qs tile
    float* s_k  = s_q + 64 * 68;    // [64][68]  Ks chunk
    float* s_v  = s_k + 64 * 68;    // [64][68]  V chunk
    float* s_p  = s_v + 64 * 68;    // [64][136] duplicated probabilities
    float* s_sk = s_p + 64 * 136;   // [64]

    const int t    = threadIdx.x;
    const int lane = t & 31;
    const int w    = t >> 5;
    const int b    = blockIdx.y;
    const int q0   = blockIdx.x * 64;

    const float* Qs = g_Qs + (size_t)b * NSEQ * 64;
    const float* Ks = g_Ks + (size_t)b * NSEQ * 64;
    const float* Vb = V    + (size_t)b * NSEQ * 64;

    for (int idx = t; idx < 64 * 16; idx += 256) {
        int r = idx >> 4, c = (idx & 15) * 4;
        *(float4*)(s_q + r * 68 + c) = *(const float4*)(Qs + (size_t)(q0 + r) * 64 + c);
    }

    float sqv[8], m[8], l[8], accx[8], accy[8];
#pragma unroll
    for (int j = 0; j < 8; j++) {
        sqv[j]  = g_sq[b * NSEQ + q0 + w * 8 + j];
        m[j]    = 1e30f;
        l[j]    = 0.f;
        accx[j] = 0.f;
        accy[j] = 0.f;
    }

    const int k0 = lane, k1 = lane + 32;

    for (int kc = 0; kc < NSEQ / 64; kc++) {
        __syncthreads();   // previous chunk fully consumed
        const int kb = kc * 64;
        for (int idx = t; idx < 64 * 16; idx += 256) {
            int r = idx >> 4, c = (idx & 15) * 4;
            *(float4*)(s_k + r * 68 + c) = *(const float4*)(Ks + (size_t)(kb + r) * 64 + c);
            *(float4*)(s_v + r * 68 + c) = *(const float4*)(Vb + (size_t)(kb + r) * 64 + c);
        }
        if (t < 64) s_sk[t] = g_sk[b * NSEQ + kb + t];
        __syncthreads();

        // ---- scores: sum_d min(Ks,Qs) for (2 k) x (8 q), float4 + packed add ----
        float t0x[8], t0y[8], t1x[8], t1y[8];
#pragma unroll
        for (int j = 0; j < 8; j++) { t0x[j] = t0y[j] = t1x[j] = t1y[j] = 0.f; }

#pragma unroll 2
        for (int d = 0; d < 64; d += 4) {
            float4 a0 = *(const float4*)(s_k + k0 * 68 + d);
            float4 a1 = *(const float4*)(s_k + k1 * 68 + d);
#pragma unroll
            for (int j = 0; j < 8; j++) {
                float4 qv = *(const float4*)(s_q + (w * 8 + j) * 68 + d);
                addx2(t0x[j], t0y[j], fminf(a0.x, qv.x), fminf(a0.y, qv.y));
                addx2(t0x[j], t0y[j], fminf(a0.z, qv.z), fminf(a0.w, qv.w));
                addx2(t1x[j], t1y[j], fminf(a1.x, qv.x), fminf(a1.y, qv.y));
                addx2(t1x[j], t1y[j], fminf(a1.z, qv.z), fminf(a1.w, qv.w));
            }
        }

        const float skk0 = s_sk[k0];
        const float skk1 = s_sk[k1];
        float p0[8], p1[8];
#pragma unroll
        for (int j = 0; j < 8; j++) {
            float s0 = skk0 + sqv[j] - 2.f * (t0x[j] + t0y[j]);
            float s1 = skk1 + sqv[j] - 2.f * (t1x[j] + t1y[j]);
            float c  = fminf(s0, s1);
#pragma unroll
            for (int off = 16; off >= 1; off >>= 1)
                c = fminf(c, __shfl_xor_sync(0xffffffffu, c, off));
            float mn    = fminf(m[j], c);
            float alpha = __expf(0.5f * (mn - m[j]) * (mn + m[j]));
            m[j]  = mn;
            p0[j] = __expf(0.5f * (mn - s0) * (mn + s0));
            p1[j] = __expf(0.5f * (mn - s1) * (mn + s1));
            float r = p0[j] + p1[j];
#pragma unroll
            for (int off = 16; off >= 1; off >>= 1)
                r += __shfl_xor_sync(0xffffffffu, r, off);
            l[j]    = l[j] * alpha + r;
            accx[j] *= alpha;
            accy[j] *= alpha;
        }

        // stash duplicated p: {p(2j),p(2j),p(2j+1),p(2j+1)} per STS.128
#pragma unroll
        for (int jj = 0; jj < 4; jj++) {
            *(float4*)(s_p + k0 * 136 + 16 * w + 4 * jj) =
                make_float4(p0[2*jj], p0[2*jj], p0[2*jj+1], p0[2*jj+1]);
            *(float4*)(s_p + k1 * 136 + 16 * w + 4 * jj) =
                make_float4(p1[2*jj], p1[2*jj], p1[2*jj+1], p1[2*jj+1]);
        }
        __syncwarp();

        // ---- AV: one broadcast LDS.128 feeds two FFMA2 ----
#pragma unroll 2
        for (int k = 0; k < 64; k++) {
            float2 v = *(const float2*)(s_v + k * 68 + 2 * lane);
#pragma unroll
            for (int jj = 0; jj < 4; jj++) {
                float4 pp = *(const float4*)(s_p + k * 136 + 16 * w + 4 * jj);
                fmax2(accx[2*jj],   accy[2*jj],   pp.x, pp.y, v.x, v.y);
                fmax2(accx[2*jj+1], accy[2*jj+1], pp.z, pp.w, v.x, v.y);
            }
        }
    }

    // epilogue: out = (acc / l) * Wo
#pragma unroll
    for (int j = 0; j < 8; j++) {
        int q = q0 + w * 8 + j;
        float inv = 1.0f / l[j];
        size_t off = ((size_t)b * NSEQ + q) * 64 + 2 * lane;
        float2 wv = *(const float2*)(g_Wo + off);
        float2 o;
        o.x = accx[j] * inv * wv.x;
        o.y = accy[j] * inv * wv.y;
        *(float2*)(out + off) = o;
    }
}

// ---------------------------------------------------------------------------
extern "C" void kernel_launch(void* const* d_in, const int* in_sizes, int n_in,
                              void* d_out, int out_size)
{
    (void)in_sizes; (void)n_in; (void)out_size;
    const float* KEY   = (const float*)d_in[0];
    const float* VALUE = (const float*)d_in[1];
    const float* QUERY = (const float*)d_in[2];
    const float* W1w = (const float*)d_in[3],  *W1b = (const float*)d_in[4];
    const float* W2w = (const float*)d_in[5],  *W2b = (const float*)d_in[6];
    const float* W3w = (const float*)d_in[7],  *W3b = (const float*)d_in[8];
    const float* O1w = (const float*)d_in[9],  *O1b = (const float*)d_in[10];
    const float* O2w = (const float*)d_in[11], *O2b = (const float*)d_in[12];
    const float* O3w = (const float*)d_in[13], *O3b = (const float*)d_in[14];

    cudaFuncSetAttribute(mlp_kernel, cudaFuncAttributeMaxDynamicSharedMemorySize,
                         MLP_SMEM_FLOATS * sizeof(float));
    cudaFuncSetAttribute(attn_kernel, cudaFuncAttributeMaxDynamicSharedMemorySize,
                         ATT_SMEM_FLOATS * sizeof(float));

    dim3 mlp_grid(NROWS / 16, 3);
    mlp_kernel<<<mlp_grid, 256, MLP_SMEM_FLOATS * sizeof(float)>>>(
        KEY, QUERY, W1w, W1b, W2w, W2b, W3w, W3b,
        O1w, O1b, O2w, O2b, O3w, O3b);

    dim3 att_grid(NSEQ / 64, NB);
    attn_kernel<<<att_grid, 256, ATT_SMEM_FLOATS * sizeof(float)>>>(
        VALUE, (float*)d_out);
}

// round 7
// speedup vs baseline: 1.1434x; 1.1434x over previous
#include <cuda_runtime.h>
#include <cuda_bf16.h>

// B=4, N=4096, D=64, H=256.
// out[b,q,dv] = (softmax_k( -0.5*cdistL1(Ks,Qs)^2 ) @ V) * Wo
//   Ks = KEY*mlp(KEY), Qs = QUERY*mlp(QUERY), Wo = mlpo(QUERY)
// L1 dist(k,q) = sk[k] + sq[q] - 2*sum_d min(Ks,Qs); flash softmax tracks min score.

#define NB   4
#define NSEQ 4096
#define DD   64
#define NROWS (NB * NSEQ)

__device__ float g_Ks[NROWS * DD];
__device__ float g_Qs[NROWS * DD];
__device__ float g_Wo[NROWS * DD];
__device__ float g_sk[NROWS];
__device__ float g_sq[NROWS];

// ---- packed fp32x2 (Blackwell FADD2/FFMA2, only reachable via PTX) ----
__device__ __forceinline__ void addx2(float& ax, float& ay, float bx, float by) {
    asm("{\n\t.reg .b64 ra, rb;\n\t"
        "mov.b64 ra, {%0, %1};\n\t"
        "mov.b64 rb, {%2, %3};\n\t"
        "add.rn.f32x2 ra, ra, rb;\n\t"
        "mov.b64 {%0, %1}, ra;\n\t}"
        : "+f"(ax), "+f"(ay) : "f"(bx), "f"(by));
}
__device__ __forceinline__ void fmax2(float& cx, float& cy, float ax, float ay,
                                      float bx, float by) {
    asm("{\n\t.reg .b64 rc, ra, rb;\n\t"
        "mov.b64 rc, {%0, %1};\n\t"
        "mov.b64 ra, {%2, %3};\n\t"
        "mov.b64 rb, {%4, %5};\n\t"
        "fma.rn.f32x2 rc, ra, rb, rc;\n\t"
        "mov.b64 {%0, %1}, rc;\n\t}"
        : "+f"(cx), "+f"(cy) : "f"(ax), "f"(ay), "f"(bx), "f"(by));
}
__device__ __forceinline__ float dupreg(float x) {
    float y;
    asm volatile("mov.f32 %0, %1;" : "=f"(y) : "f"(x));
    return y;
}

// ---------------------------------------------------------------------------
// MLP kernel. One block = 64 rows, 512 threads, occ 1 (217KB smem).
// mode: 0 KEY->Ks,sk ; 1 QUERY->Qs,sq ; 2 QUERY->Wo.
// Layers 64 ->256 relu -> 256 relu -> 64. Weight chunks staged transposed.
// ---------------------------------------------------------------------------
#define MLP_SMEM_FLOATS (64*68 + 64*260 + 64*260 + 64*260)

__global__ void __launch_bounds__(512, 1) mlp_kernel(
    const float* __restrict__ KEY, const float* __restrict__ QUERY,
    const float* __restrict__ W1,  const float* __restrict__ B1,
    const float* __restrict__ W2,  const float* __restrict__ B2,
    const float* __restrict__ W3,  const float* __restrict__ B3,
    const float* __restrict__ W1o, const float* __restrict__ B1o,
    const float* __restrict__ W2o, const float* __restrict__ B2o,
    const float* __restrict__ W3o, const float* __restrict__ B3o)
{
    extern __shared__ float sm[];
    float* s_x = sm;              // 64*68
    float* s_a = s_x + 64 * 68;   // 64*260
    float* s_b = s_a + 64 * 260;  // 64*260
    float* s_w = s_b + 64 * 260;  // 64*260 (transposed weight chunk [in][out])

    const int t    = threadIdx.x;
    const int mode = blockIdx.y;
    const int row0 = blockIdx.x * 64;

    const float* X  = (mode == 0) ? KEY : QUERY;
    const float* w1 = (mode < 2) ? W1 : W1o;
    const float* b1 = (mode < 2) ? B1 : B1o;
    const float* w2 = (mode < 2) ? W2 : W2o;
    const float* b2 = (mode < 2) ? B2 : B2o;
    const float* w3 = (mode < 2) ? W3 : W3o;
    const float* b3 = (mode < 2) ? B3 : B3o;

    // input tile 64x64
    for (int idx = t; idx < 64 * 16; idx += 512) {
        int r = idx >> 4, c = (idx & 15) * 4;
        *(float4*)(s_x + r * 68 + c) =
            *(const float4*)(X + (size_t)(row0 + r) * 64 + c);
    }
    // stage W1 (256x64) transposed
    for (int idx = t; idx < 256 * 64; idx += 512) {
        int o = idx >> 6, i = idx & 63;
        s_w[i * 260 + o] = w1[idx];
    }
    __syncthreads();

    const int og = t & 31;   // 32 out-groups of 8 outs
    const int rg = t >> 5;   // 16 row-groups of 4 rows

    // ================= Layer 1: 64 -> 256, relu -> s_a =================
    {
        float acc[4][8];
#pragma unroll
        for (int r = 0; r < 4; r++)
#pragma unroll
            for (int c = 0; c < 8; c++) acc[r][c] = 0.f;

#pragma unroll 4
        for (int i = 0; i < 64; i++) {
            float a0 = s_x[(rg * 4 + 0) * 68 + i];
            float a1 = s_x[(rg * 4 + 1) * 68 + i];
            float a2 = s_x[(rg * 4 + 2) * 68 + i];
            float a3 = s_x[(rg * 4 + 3) * 68 + i];
            float a0d = dupreg(a0), a1d = dupreg(a1), a2d = dupreg(a2), a3d = dupreg(a3);
            float4 wA = *(const float4*)(s_w + i * 260 + og * 8);
            float4 wB = *(const float4*)(s_w + i * 260 + og * 8 + 4);
            fmax2(acc[0][0], acc[0][1], a0, a0d, wA.x, wA.y);
            fmax2(acc[0][2], acc[0][3], a0, a0d, wA.z, wA.w);
            fmax2(acc[0][4], acc[0][5], a0, a0d, wB.x, wB.y);
            fmax2(acc[0][6], acc[0][7], a0, a0d, wB.z, wB.w);
            fmax2(acc[1][0], acc[1][1], a1, a1d, wA.x, wA.y);
            fmax2(acc[1][2], acc[1][3], a1, a1d, wA.z, wA.w);
            fmax2(acc[1][4], acc[1][5], a1, a1d, wB.x, wB.y);
            fmax2(acc[1][6], acc[1][7], a1, a1d, wB.z, wB.w);
            fmax2(acc[2][0], acc[2][1], a2, a2d, wA.x, wA.y);
            fmax2(acc[2][2], acc[2][3], a2, a2d, wA.z, wA.w);
            fmax2(acc[2][4], acc[2][5], a2, a2d, wB.x, wB.y);
            fmax2(acc[2][6], acc[2][7], a2, a2d, wB.z, wB.w);
            fmax2(acc[3][0], acc[3][1], a3, a3d, wA.x, wA.y);
            fmax2(acc[3][2], acc[3][3], a3, a3d, wA.z, wA.w);
            fmax2(acc[3][4], acc[3][5], a3, a3d, wB.x, wB.y);
            fmax2(acc[3][6], acc[3][7], a3, a3d, wB.z, wB.w);
        }
#pragma unroll
        for (int c = 0; c < 8; c++) {
            int o = og * 8 + c;
            float bv = __ldg(b1 + o);
#pragma unroll
            for (int r = 0; r < 4; r++)
                s_a[(rg * 4 + r) * 260 + o] = fmaxf(acc[r][c] + bv, 0.f);
        }
    }

    // ================= Layer 2: 256 -> 256, relu -> s_b =================
    {
        float acc[4][8];
#pragma unroll
        for (int r = 0; r < 4; r++)
#pragma unroll
            for (int c = 0; c < 8; c++) acc[r][c] = 0.f;

        for (int ch = 0; ch < 4; ch++) {
            __syncthreads();
            for (int idx = t; idx < 256 * 64; idx += 512) {
                int o = idx >> 6, i = idx & 63;
                s_w[i * 260 + o] = w2[o * 256 + ch * 64 + i];
            }
            __syncthreads();
#pragma unroll 4
            for (int i = 0; i < 64; i++) {
                float a0 = s_a[(rg * 4 + 0) * 260 + ch * 64 + i];
                float a1 = s_a[(rg * 4 + 1) * 260 + ch * 64 + i];
                float a2 = s_a[(rg * 4 + 2) * 260 + ch * 64 + i];
                float a3 = s_a[(rg * 4 + 3) * 260 + ch * 64 + i];
                float a0d = dupreg(a0), a1d = dupreg(a1), a2d = dupreg(a2), a3d = dupreg(a3);
                float4 wA = *(const float4*)(s_w + i * 260 + og * 8);
                float4 wB = *(const float4*)(s_w + i * 260 + og * 8 + 4);
                fmax2(acc[0][0], acc[0][1], a0, a0d, wA.x, wA.y);
                fmax2(acc[0][2], acc[0][3], a0, a0d, wA.z, wA.w);
                fmax2(acc[0][4], acc[0][5], a0, a0d, wB.x, wB.y);
                fmax2(acc[0][6], acc[0][7], a0, a0d, wB.z, wB.w);
                fmax2(acc[1][0], acc[1][1], a1, a1d, wA.x, wA.y);
                fmax2(acc[1][2], acc[1][3], a1, a1d, wA.z, wA.w);
                fmax2(acc[1][4], acc[1][5], a1, a1d, wB.x, wB.y);
                fmax2(acc[1][6], acc[1][7], a1, a1d, wB.z, wB.w);
                fmax2(acc[2][0], acc[2][1], a2, a2d, wA.x, wA.y);
                fmax2(acc[2][2], acc[2][3], a2, a2d, wA.z, wA.w);
                fmax2(acc[2][4], acc[2][5], a2, a2d, wB.x, wB.y);
                fmax2(acc[2][6], acc[2][7], a2, a2d, wB.z, wB.w);
                fmax2(acc[3][0], acc[3][1], a3, a3d, wA.x, wA.y);
                fmax2(acc[3][2], acc[3][3], a3, a3d, wA.z, wA.w);
                fmax2(acc[3][4], acc[3][5], a3, a3d, wB.x, wB.y);
                fmax2(acc[3][6], acc[3][7], a3, a3d, wB.z, wB.w);
            }
        }
#pragma unroll
        for (int c = 0; c < 8; c++) {
            int o = og * 8 + c;
            float bv = __ldg(b2 + o);
#pragma unroll
            for (int r = 0; r < 4; r++)
                s_b[(rg * 4 + r) * 260 + o] = fmaxf(acc[r][c] + bv, 0.f);
        }
    }

    // ================= Layer 3: 256 -> 64 + epilogue =================
    {
        const int row = t >> 3;   // 64 rows, 8 threads each
        const int o8  = t & 7;    // 8 out-groups of 8 outs
        float acc3[8];
#pragma unroll
        for (int c = 0; c < 8; c++) acc3[c] = 0.f;

        for (int ch = 0; ch < 4; ch++) {
            __syncthreads();
            for (int idx = t; idx < 64 * 64; idx += 512) {
                int o = idx >> 6, i = idx & 63;
                s_w[i * 260 + o] = w3[o * 256 + ch * 64 + i];
            }
            __syncthreads();
#pragma unroll 4
            for (int i = 0; i < 64; i++) {
                float a = s_b[row * 260 + ch * 64 + i];
                float ad = dupreg(a);
                float4 wA = *(const float4*)(s_w + i * 260 + o8 * 8);
                float4 wB = *(const float4*)(s_w + i * 260 + o8 * 8 + 4);
                fmax2(acc3[0], acc3[1], a, ad, wA.x, wA.y);
                fmax2(acc3[2], acc3[3], a, ad, wA.z, wA.w);
                fmax2(acc3[4], acc3[5], a, ad, wB.x, wB.y);
                fmax2(acc3[6], acc3[7], a, ad, wB.z, wB.w);
            }
        }

        float val[8];
        float sum = 0.f;
#pragma unroll
        for (int c = 0; c < 8; c++) {
            int o = o8 * 8 + c;
            float y = acc3[c] + __ldg(b3 + o);
            if (mode < 2) { val[c] = y * s_x[row * 68 + o]; sum += val[c]; }
            else          { val[c] = y; }
        }
        float* dst = (mode == 0) ? g_Ks : (mode == 1) ? g_Qs : g_Wo;
        size_t grow = (size_t)(row0 + row);
        *(float4*)(dst + grow * 64 + o8 * 8)     = make_float4(val[0], val[1], val[2], val[3]);
        *(float4*)(dst + grow * 64 + o8 * 8 + 4) = make_float4(val[4], val[5], val[6], val[7]);
        if (mode < 2) {
            sum += __shfl_xor_sync(0xffffffffu, sum, 1);
            sum += __shfl_xor_sync(0xffffffffu, sum, 2);
            sum += __shfl_xor_sync(0xffffffffu, sum, 4);
            if (o8 == 0) ((mode == 0) ? g_sk : g_sq)[grow] = sum;
        }
    }
}

// ---------------------------------------------------------------------------
// Attention. Block = 64 queries (8 warps x 8 q), key chunks of 64.
// Lane owns 2 keys for scores, dv pair {2*lane,2*lane+1} for AV.
// l kept as PER-LANE partial (reduced once at the end); alpha path skipped
// via warp-uniform branch when the running min didn't change.
// ---------------------------------------------------------------------------
#define ATT_SMEM_FLOATS (64*68 + 64*68 + 64*68 + 64*136 + 64)

__global__ void __launch_bounds__(256, 2) attn_kernel(
    const float* __restrict__ V, float* __restrict__ out)
{
    extern __shared__ float sm[];
    float* s_q  = sm;               // [64][68]  Qs tile
    float* s_k  = s_q + 64 * 68;    // [64][68]  Ks chunk
    float* s_v  = s_k + 64 * 68;    // [64][68]  V chunk
    float* s_p  = s_v + 64 * 68;    // [64][136] duplicated probabilities
    float* s_sk = s_p + 64 * 136;   // [64]

    const int t    = threadIdx.x;
    const int lane = t & 31;
    const int w    = t >> 5;
    const int b    = blockIdx.y;
    const int q0   = blockIdx.x * 64;

    const float* Qs = g_Qs + (size_t)b * NSEQ * 64;
    const float* Ks = g_Ks + (size_t)b * NSEQ * 64;
    const float* Vb = V    + (size_t)b * NSEQ * 64;

    for (int idx = t; idx < 64 * 16; idx += 256) {
        int r = idx >> 4, c = (idx & 15) * 4;
        *(float4*)(s_q + r * 68 + c) = *(const float4*)(Qs + (size_t)(q0 + r) * 64 + c);
    }

    float sqv[8], m[8], l[8], accx[8], accy[8];
#pragma unroll
    for (int j = 0; j < 8; j++) {
        sqv[j]  = g_sq[b * NSEQ + q0 + w * 8 + j];
        m[j]    = 1e30f;
        l[j]    = 0.f;       // per-lane partial (its 2 keys)
        accx[j] = 0.f;
        accy[j] = 0.f;
    }

    const int k0 = lane, k1 = lane + 32;

    for (int kc = 0; kc < NSEQ / 64; kc++) {
        __syncthreads();   // previous chunk fully consumed
        const int kb = kc * 64;
        for (int idx = t; idx < 64 * 16; idx += 256) {
            int r = idx >> 4, c = (idx & 15) * 4;
            *(float4*)(s_k + r * 68 + c) = *(const float4*)(Ks + (size_t)(kb + r) * 64 + c);
            *(float4*)(s_v + r * 68 + c) = *(const float4*)(Vb + (size_t)(kb + r) * 64 + c);
        }
        if (t < 64) s_sk[t] = g_sk[b * NSEQ + kb + t];
        __syncthreads();

        // ---- scores: sum_d min(Ks,Qs) for (2 k) x (8 q), float4 + packed add ----
        float t0x[8], t0y[8], t1x[8], t1y[8];
#pragma unroll
        for (int j = 0; j < 8; j++) { t0x[j] = t0y[j] = t1x[j] = t1y[j] = 0.f; }

#pragma unroll 2
        for (int d = 0; d < 64; d += 4) {
            float4 a0 = *(const float4*)(s_k + k0 * 68 + d);
            float4 a1 = *(const float4*)(s_k + k1 * 68 + d);
#pragma unroll
            for (int j = 0; j < 8; j++) {
                float4 qv = *(const float4*)(s_q + (w * 8 + j) * 68 + d);
                addx2(t0x[j], t0y[j], fminf(a0.x, qv.x), fminf(a0.y, qv.y));
                addx2(t0x[j], t0y[j], fminf(a0.z, qv.z), fminf(a0.w, qv.w));
                addx2(t1x[j], t1y[j], fminf(a1.x, qv.x), fminf(a1.y, qv.y));
                addx2(t1x[j], t1y[j], fminf(a1.z, qv.z), fminf(a1.w, qv.w));
            }
        }

        const float skk0 = s_sk[k0];
        const float skk1 = s_sk[k1];
        float p0[8], p1[8];
#pragma unroll
        for (int j = 0; j < 8; j++) {
            float s0 = skk0 + sqv[j] - 2.f * (t0x[j] + t0y[j]);
            float s1 = skk1 + sqv[j] - 2.f * (t1x[j] + t1y[j]);
            float c  = fminf(s0, s1);
#pragma unroll
            for (int off = 16; off >= 1; off >>= 1)
                c = fminf(c, __shfl_xor_sync(0xffffffffu, c, off));
            float mn = fminf(m[j], c);
            if (mn != m[j]) {                     // warp-uniform branch
                float alpha = __expf(0.5f * (mn - m[j]) * (mn + m[j]));
                m[j] = mn;
                l[j]    *= alpha;
                accx[j] *= alpha;
                accy[j] *= alpha;
            }
            p0[j] = __expf(0.5f * (mn - s0) * (mn + s0));
            p1[j] = __expf(0.5f * (mn - s1) * (mn + s1));
            l[j] += p0[j] + p1[j];                // per-lane partial, no shuffle
        }

        // stash duplicated p: {p(2j),p(2j),p(2j+1),p(2j+1)} per STS.128
#pragma unroll
        for (int jj = 0; jj < 4; jj++) {
            *(float4*)(s_p + k0 * 136 + 16 * w + 4 * jj) =
                make_float4(p0[2*jj], p0[2*jj], p0[2*jj+1], p0[2*jj+1]);
            *(float4*)(s_p + k1 * 136 + 16 * w + 4 * jj) =
                make_float4(p1[2*jj], p1[2*jj], p1[2*jj+1], p1[2*jj+1]);
        }
        __syncwarp();

        // ---- AV: one broadcast LDS.128 feeds two FFMA2 ----
#pragma unroll 2
        for (int k = 0; k < 64; k++) {
            float2 v = *(const float2*)(s_v + k * 68 + 2 * lane);
#pragma unroll
            for (int jj = 0; jj < 4; jj++) {
                float4 pp = *(const float4*)(s_p + k * 136 + 16 * w + 4 * jj);
                fmax2(accx[2*jj],   accy[2*jj],   pp.x, pp.y, v.x, v.y);
                fmax2(accx[2*jj+1], accy[2*jj+1], pp.z, pp.w, v.x, v.y);
            }
        }
    }

    // final l reduction across lanes (once), then epilogue out = (acc/l)*Wo
#pragma unroll
    for (int j = 0; j < 8; j++) {
        float r = l[j];
#pragma unroll
        for (int off = 16; off >= 1; off >>= 1)
            r += __shfl_xor_sync(0xffffffffu, r, off);
        int q = q0 + w * 8 + j;
        float inv = 1.0f / r;
        size_t off2 = ((size_t)b * NSEQ + q) * 64 + 2 * lane;
        float2 wv = *(const float2*)(g_Wo + off2);
        float2 o;
        o.x = accx[j] * inv * wv.x;
        o.y = accy[j] * inv * wv.y;
        *(float2*)(out + off2) = o;
    }
}

// ---------------------------------------------------------------------------
extern "C" void kernel_launch(void* const* d_in, const int* in_sizes, int n_in,
                              void* d_out, int out_size)
{
    (void)in_sizes; (void)n_in; (void)out_size;
    const float* KEY   = (const float*)d_in[0];
    const float* VALUE = (const float*)d_in[1];
    const float* QUERY = (const float*)d_in[2];
    const float* W1w = (const float*)d_in[3],  *W1b = (const float*)d_in[4];
    const float* W2w = (const float*)d_in[5],  *W2b = (const float*)d_in[6];
    const float* W3w = (const float*)d_in[7],  *W3b = (const float*)d_in[8];
    const float* O1w = (const float*)d_in[9],  *O1b = (const float*)d_in[10];
    const float* O2w = (const float*)d_in[11], *O2b = (const float*)d_in[12];
    const float* O3w = (const float*)d_in[13], *O3b = (const float*)d_in[14];

    cudaFuncSetAttribute(mlp_kernel, cudaFuncAttributeMaxDynamicSharedMemorySize,
                         MLP_SMEM_FLOATS * sizeof(float));
    cudaFuncSetAttribute(attn_kernel, cudaFuncAttributeMaxDynamicSharedMemorySize,
                         ATT_SMEM_FLOATS * sizeof(float));

    dim3 mlp_grid(NROWS / 64, 3);
    mlp_kernel<<<mlp_grid, 512, MLP_SMEM_FLOATS * sizeof(float)>>>(
        KEY, QUERY, W1w, W1b, W2w, W2b, W3w, W3b,
        O1w, O1b, O2w, O2b, O3w, O3b);

    dim3 att_grid(NSEQ / 64, NB);
    attn_kernel<<<att_grid, 256, ATT_SMEM_FLOATS * sizeof(float)>>>(
        VALUE, (float*)d_out);
}

// round 9
// speedup vs baseline: 1.3636x; 1.1926x over previous
#include <cuda_runtime.h>
#include <cuda_bf16.h>

// B=4, N=4096, D=64, H=256.
// out[b,q,dv] = (softmax_k( -0.5*cdistL1(Ks,Qs)^2 ) @ V) * Wo
//   Ks = KEY*mlp(KEY), Qs = QUERY*mlp(QUERY), Wo = mlpo(QUERY)
// L1 dist(k,q) = sk[k] + sq[q] - 2*sum_d min(Ks,Qs); flash softmax tracks min score.

#define NB   4
#define NSEQ 4096
#define DD   64
#define NROWS (NB * NSEQ)

__device__ float g_Ks[NROWS * DD];
__device__ float g_Qs[NROWS * DD];
__device__ float g_Wo[NROWS * DD];
__device__ float g_sk[NROWS];
__device__ float g_sq[NROWS];

// ---- packed fp32x2 (Blackwell FADD2/FFMA2, only reachable via PTX) ----
__device__ __forceinline__ void addx2(float& ax, float& ay, float bx, float by) {
    asm("{\n\t.reg .b64 ra, rb;\n\t"
        "mov.b64 ra, {%0, %1};\n\t"
        "mov.b64 rb, {%2, %3};\n\t"
        "add.rn.f32x2 ra, ra, rb;\n\t"
        "mov.b64 {%0, %1}, ra;\n\t}"
        : "+f"(ax), "+f"(ay) : "f"(bx), "f"(by));
}
__device__ __forceinline__ void fmax2(float& cx, float& cy, float ax, float ay,
                                      float bx, float by) {
    asm("{\n\t.reg .b64 rc, ra, rb;\n\t"
        "mov.b64 rc, {%0, %1};\n\t"
        "mov.b64 ra, {%2, %3};\n\t"
        "mov.b64 rb, {%4, %5};\n\t"
        "fma.rn.f32x2 rc, ra, rb, rc;\n\t"
        "mov.b64 {%0, %1}, rc;\n\t}"
        : "+f"(cx), "+f"(cy) : "f"(ax), "f"(ay), "f"(bx), "f"(by));
}
__device__ __forceinline__ float dupreg(float x) {
    float y;
    asm volatile("mov.f32 %0, %1;" : "=f"(y) : "f"(x));
    return y;
}

// ---------------------------------------------------------------------------
// MLP kernel. One block = 64 rows, 256 threads, occ 1 (217KB smem).
// Per-thread tile 8 rows x 8 outs -> 32 FFMA2 per i-step (fma-pipe bound).
// mode: 0 KEY->Ks,sk ; 1 QUERY->Qs,sq ; 2 QUERY->Wo.
// ---------------------------------------------------------------------------
#define MLP_SMEM_FLOATS (64*68 + 64*260 + 64*260 + 64*260)

__global__ void __launch_bounds__(256, 1) mlp_kernel(
    const float* __restrict__ KEY, const float* __restrict__ QUERY,
    const float* __restrict__ W1,  const float* __restrict__ B1,
    const float* __restrict__ W2,  const float* __restrict__ B2,
    const float* __restrict__ W3,  const float* __restrict__ B3,
    const float* __restrict__ W1o, const float* __restrict__ B1o,
    const float* __restrict__ W2o, const float* __restrict__ B2o,
    const float* __restrict__ W3o, const float* __restrict__ B3o)
{
    extern __shared__ float sm[];
    float* s_x = sm;              // 64*68
    float* s_a = s_x + 64 * 68;   // 64*260
    float* s_b = s_a + 64 * 260;  // 64*260
    float* s_w = s_b + 64 * 260;  // 64*260 (transposed weight chunk [in][out])

    const int t    = threadIdx.x;
    const int mode = blockIdx.y;
    const int row0 = blockIdx.x * 64;

    const float* X  = (mode == 0) ? KEY : QUERY;
    const float* w1 = (mode < 2) ? W1 : W1o;
    const float* b1 = (mode < 2) ? B1 : B1o;
    const float* w2 = (mode < 2) ? W2 : W2o;
    const float* b2 = (mode < 2) ? B2 : B2o;
    const float* w3 = (mode < 2) ? W3 : W3o;
    const float* b3 = (mode < 2) ? B3 : B3o;

    // input tile 64x64
    for (int idx = t; idx < 64 * 16; idx += 256) {
        int r = idx >> 4, c = (idx & 15) * 4;
        *(float4*)(s_x + r * 68 + c) =
            *(const float4*)(X + (size_t)(row0 + r) * 64 + c);
    }
    // stage W1 (256x64) transposed
    for (int idx = t; idx < 256 * 64; idx += 256) {
        int o = idx >> 6, i = idx & 63;
        s_w[i * 260 + o] = w1[idx];
    }
    __syncthreads();

    const int og = t & 31;   // 32 out-groups of 8 outs
    const int rg = t >> 5;   // 8 row-groups of 8 rows

    // ================= Layer 1: 64 -> 256, relu -> s_a =================
    {
        float acc[8][8];
#pragma unroll
        for (int r = 0; r < 8; r++)
#pragma unroll
            for (int c = 0; c < 8; c++) acc[r][c] = 0.f;

#pragma unroll 2
        for (int i = 0; i < 64; i++) {
            float4 wA = *(const float4*)(s_w + i * 260 + og * 8);
            float4 wB = *(const float4*)(s_w + i * 260 + og * 8 + 4);
#pragma unroll
            for (int r = 0; r < 8; r++) {
                float a  = s_x[(rg * 8 + r) * 68 + i];
                float ad = dupreg(a);
                fmax2(acc[r][0], acc[r][1], a, ad, wA.x, wA.y);
                fmax2(acc[r][2], acc[r][3], a, ad, wA.z, wA.w);
                fmax2(acc[r][4], acc[r][5], a, ad, wB.x, wB.y);
                fmax2(acc[r][6], acc[r][7], a, ad, wB.z, wB.w);
            }
        }
#pragma unroll
        for (int c = 0; c < 8; c++) {
            int o = og * 8 + c;
            float bv = __ldg(b1 + o);
#pragma unroll
            for (int r = 0; r < 8; r++)
                s_a[(rg * 8 + r) * 260 + o] = fmaxf(acc[r][c] + bv, 0.f);
        }
    }

    // ================= Layer 2: 256 -> 256, relu -> s_b =================
    {
        float acc[8][8];
#pragma unroll
        for (int r = 0; r < 8; r++)
#pragma unroll
            for (int c = 0; c < 8; c++) acc[r][c] = 0.f;

        for (int ch = 0; ch < 4; ch++) {
            __syncthreads();
            for (int idx = t; idx < 256 * 64; idx += 256) {
                int o = idx >> 6, i = idx & 63;
                s_w[i * 260 + o] = w2[o * 256 + ch * 64 + i];
            }
            __syncthreads();
#pragma unroll 2
            for (int i = 0; i < 64; i++) {
                float4 wA = *(const float4*)(s_w + i * 260 + og * 8);
                float4 wB = *(const float4*)(s_w + i * 260 + og * 8 + 4);
#pragma unroll
                for (int r = 0; r < 8; r++) {
                    float a  = s_a[(rg * 8 + r) * 260 + ch * 64 + i];
                    float ad = dupreg(a);
                    fmax2(acc[r][0], acc[r][1], a, ad, wA.x, wA.y);
                    fmax2(acc[r][2], acc[r][3], a, ad, wA.z, wA.w);
                    fmax2(acc[r][4], acc[r][5], a, ad, wB.x, wB.y);
                    fmax2(acc[r][6], acc[r][7], a, ad, wB.z, wB.w);
                }
            }
        }
#pragma unroll
        for (int c = 0; c < 8; c++) {
            int o = og * 8 + c;
            float bv = __ldg(b2 + o);
#pragma unroll
            for (int r = 0; r < 8; r++)
                s_b[(rg * 8 + r) * 260 + o] = fmaxf(acc[r][c] + bv, 0.f);
        }
    }

    // ================= Layer 3: 256 -> 64 + epilogue =================
    {
        const int rp = t >> 3;    // 32 row-pairs (2 rows each)
        const int o8 = t & 7;     // 8 out-groups of 8 outs
        float acc3[2][8];
#pragma unroll
        for (int r = 0; r < 2; r++)
#pragma unroll
            for (int c = 0; c < 8; c++) acc3[r][c] = 0.f;

        for (int ch = 0; ch < 4; ch++) {
            __syncthreads();
            for (int idx = t; idx < 64 * 64; idx += 256) {
                int o = idx >> 6, i = idx & 63;
                s_w[i * 260 + o] = w3[o * 256 + ch * 64 + i];
            }
            __syncthreads();
#pragma unroll 4
            for (int i = 0; i < 64; i++) {
                float4 wA = *(const float4*)(s_w + i * 260 + o8 * 8);
                float4 wB = *(const float4*)(s_w + i * 260 + o8 * 8 + 4);
#pragma unroll
                for (int r = 0; r < 2; r++) {
                    float a  = s_b[(rp * 2 + r) * 260 + ch * 64 + i];
                    float ad = dupreg(a);
                    fmax2(acc3[r][0], acc3[r][1], a, ad, wA.x, wA.y);
                    fmax2(acc3[r][2], acc3[r][3], a, ad, wA.z, wA.w);
                    fmax2(acc3[r][4], acc3[r][5], a, ad, wB.x, wB.y);
                    fmax2(acc3[r][6], acc3[r][7], a, ad, wB.z, wB.w);
                }
            }
        }

        float* dst = (mode == 0) ? g_Ks : (mode == 1) ? g_Qs : g_Wo;
#pragma unroll
        for (int r = 0; r < 2; r++) {
            const int row = rp * 2 + r;
            float val[8];
            float sum = 0.f;
#pragma unroll
            for (int c = 0; c < 8; c++) {
                int o = o8 * 8 + c;
                float y = acc3[r][c] + __ldg(b3 + o);
                if (mode < 2) { val[c] = y * s_x[row * 68 + o]; sum += val[c]; }
                else          { val[c] = y; }
            }
            size_t grow = (size_t)(row0 + row);
            *(float4*)(dst + grow * 64 + o8 * 8)     = make_float4(val[0], val[1], val[2], val[3]);
            *(float4*)(dst + grow * 64 + o8 * 8 + 4) = make_float4(val[4], val[5], val[6], val[7]);
            if (mode < 2) {
                sum += __shfl_xor_sync(0xffffffffu, sum, 1);
                sum += __shfl_xor_sync(0xffffffffu, sum, 2);
                sum += __shfl_xor_sync(0xffffffffu, sum, 4);
                if (o8 == 0) ((mode == 0) ? g_sk : g_sq)[grow] = sum;
            }
        }
    }
}

// ---------------------------------------------------------------------------
// Attention. Block = 64 queries (8 warps x 8 q), key chunks of 64, occ 3.
// Lane owns 2 keys for scores, dv pair {2*lane,2*lane+1} for AV.
// Score loop split into two j-groups of 4 (register pressure); p stored plain;
// AV packs accumulators over q-pairs with duplicated v operand.
// ---------------------------------------------------------------------------
#define ATT_SMEM_FLOATS (64*68 * 4 + 64 + 64)

__global__ void __launch_bounds__(256, 3) attn_kernel(
    const float* __restrict__ V, float* __restrict__ out)
{
    extern __shared__ float sm[];
    float* s_q  = sm;               // [64][68]  Qs tile
    float* s_k  = s_q + 64 * 68;    // [64][68]  Ks chunk
    float* s_v  = s_k + 64 * 68;    // [64][68]  V chunk
    float* s_p  = s_v + 64 * 68;    // [64][68]  probabilities (plain, col = w*8+j)
    float* s_sk = s_p + 64 * 68;    // [64]
    float* s_sq = s_sk + 64;        // [64]

    const int t    = threadIdx.x;
    const int lane = t & 31;
    const int w    = t >> 5;
    const int w8   = w * 8;
    const int b    = blockIdx.y;
    const int q0   = blockIdx.x * 64;

    const float* Qs = g_Qs + (size_t)b * NSEQ * 64;
    const float* Ks = g_Ks + (size_t)b * NSEQ * 64;
    const float* Vb = V    + (size_t)b * NSEQ * 64;

    for (int idx = t; idx < 64 * 16; idx += 256) {
        int r = idx >> 4, c = (idx & 15) * 4;
        *(float4*)(s_q + r * 68 + c) = *(const float4*)(Qs + (size_t)(q0 + r) * 64 + c);
    }
    if (t < 64) s_sq[t] = g_sq[b * NSEQ + q0 + t];

    float m[8], l[8], accx[8], accy[8];
#pragma unroll
    for (int j = 0; j < 8; j++) {
        m[j] = 1e30f; l[j] = 0.f; accx[j] = 0.f; accy[j] = 0.f;
    }

    const int k0 = lane, k1 = lane + 32;

    for (int kc = 0; kc < NSEQ / 64; kc++) {
        __syncthreads();   // previous chunk fully consumed
        const int kb = kc * 64;
        for (int idx = t; idx < 64 * 16; idx += 256) {
            int r = idx >> 4, c = (idx & 15) * 4;
            *(float4*)(s_k + r * 68 + c) = *(const float4*)(Ks + (size_t)(kb + r) * 64 + c);
            *(float4*)(s_v + r * 68 + c) = *(const float4*)(Vb + (size_t)(kb + r) * 64 + c);
        }
        if (t < 64) s_sk[t] = g_sk[b * NSEQ + kb + t];
        __syncthreads();

        // ---- scores in two j-groups of 4 (fewer live registers) ----
#pragma unroll
        for (int g = 0; g < 2; g++) {
            float t0x[4], t0y[4], t1x[4], t1y[4];
#pragma unroll
            for (int j = 0; j < 4; j++) { t0x[j] = t0y[j] = t1x[j] = t1y[j] = 0.f; }

#pragma unroll 2
            for (int d = 0; d < 64; d += 4) {
                float4 a0 = *(const float4*)(s_k + k0 * 68 + d);
                float4 a1 = *(const float4*)(s_k + k1 * 68 + d);
#pragma unroll
                for (int j = 0; j < 4; j++) {
                    float4 qv = *(const float4*)(s_q + (w8 + g * 4 + j) * 68 + d);
                    addx2(t0x[j], t0y[j], fminf(a0.x, qv.x), fminf(a0.y, qv.y));
                    addx2(t0x[j], t0y[j], fminf(a0.z, qv.z), fminf(a0.w, qv.w));
                    addx2(t1x[j], t1y[j], fminf(a1.x, qv.x), fminf(a1.y, qv.y));
                    addx2(t1x[j], t1y[j], fminf(a1.z, qv.z), fminf(a1.w, qv.w));
                }
            }

            const float skk0 = s_sk[k0];
            const float skk1 = s_sk[k1];
            float p0[4], p1[4];
#pragma unroll
            for (int j = 0; j < 4; j++) {
                const int jq = g * 4 + j;
                float sqj = s_sq[w8 + jq];
                float s0 = skk0 + sqj - 2.f * (t0x[j] + t0y[j]);
                float s1 = skk1 + sqj - 2.f * (t1x[j] + t1y[j]);
                float c  = fminf(s0, s1);
#pragma unroll
                for (int off = 16; off >= 1; off >>= 1)
                    c = fminf(c, __shfl_xor_sync(0xffffffffu, c, off));
                float mn = fminf(m[jq], c);
                if (mn != m[jq]) {                 // warp-uniform branch
                    float alpha = __expf(0.5f * (mn - m[jq]) * (mn + m[jq]));
                    m[jq] = mn;
                    l[jq]    *= alpha;
                    accx[jq] *= alpha;
                    accy[jq] *= alpha;
                }
                p0[j] = __expf(0.5f * (mn - s0) * (mn + s0));
                p1[j] = __expf(0.5f * (mn - s1) * (mn + s1));
                l[jq] += p0[j] + p1[j];            // per-lane partial
            }
            *(float4*)(s_p + k0 * 68 + w8 + g * 4) = make_float4(p0[0], p0[1], p0[2], p0[3]);
            *(float4*)(s_p + k1 * 68 + w8 + g * 4) = make_float4(p1[0], p1[1], p1[2], p1[3]);
        }
        __syncwarp();

        // ---- AV: q-pair-packed accumulators, duplicated v operand ----
#pragma unroll 2
        for (int k = 0; k < 64; k++) {
            float4 pA = *(const float4*)(s_p + k * 68 + w8);
            float4 pB = *(const float4*)(s_p + k * 68 + w8 + 4);
            float2 v  = *(const float2*)(s_v + k * 68 + 2 * lane);
            float vdx = dupreg(v.x), vdy = dupreg(v.y);
            fmax2(accx[0], accx[1], pA.x, pA.y, v.x, vdx);
            fmax2(accx[2], accx[3], pA.z, pA.w, v.x, vdx);
            fmax2(accx[4], accx[5], pB.x, pB.y, v.x, vdx);
            fmax2(accx[6], accx[7], pB.z, pB.w, v.x, vdx);
            fmax2(accy[0], accy[1], pA.x, pA.y, v.y, vdy);
            fmax2(accy[2], accy[3], pA.z, pA.w, v.y, vdy);
            fmax2(accy[4], accy[5], pB.x, pB.y, v.y, vdy);
            fmax2(accy[6], accy[7], pB.z, pB.w, v.y, vdy);
        }
    }

    // final l reduction across lanes, then epilogue out = (acc/l)*Wo
#pragma unroll
    for (int j = 0; j < 8; j++) {
        float r = l[j];
#pragma unroll
        for (int off = 16; off >= 1; off >>= 1)
            r += __shfl_xor_sync(0xffffffffu, r, off);
        int q = q0 + w8 + j;
        float inv = 1.0f / r;
        size_t off2 = ((size_t)b * NSEQ + q) * 64 + 2 * lane;
        float2 wv = *(const float2*)(g_Wo + off2);
        float2 o;
        o.x = accx[j] * inv * wv.x;
        o.y = accy[j] * inv * wv.y;
        *(float2*)(out + off2) = o;
    }
}

// ---------------------------------------------------------------------------
extern "C" void kernel_launch(void* const* d_in, const int* in_sizes, int n_in,
                              void* d_out, int out_size)
{
    (void)in_sizes; (void)n_in; (void)out_size;
    const float* KEY   = (const float*)d_in[0];
    const float* VALUE = (const float*)d_in[1];
    const float* QUERY = (const float*)d_in[2];
    const float* W1w = (const float*)d_in[3],  *W1b = (const float*)d_in[4];
    const float* W2w = (const float*)d_in[5],  *W2b = (const float*)d_in[6];
    const float* W3w = (const float*)d_in[7],  *W3b = (const float*)d_in[8];
    const float* O1w = (const float*)d_in[9],  *O1b = (const float*)d_in[10];
    const float* O2w = (const float*)d_in[11], *O2b = (const float*)d_in[12];
    const float* O3w = (const float*)d_in[13], *O3b = (const float*)d_in[14];

    cudaFuncSetAttribute(mlp_kernel, cudaFuncAttributeMaxDynamicSharedMemorySize,
                         MLP_SMEM_FLOATS * sizeof(float));
    cudaFuncSetAttribute(attn_kernel, cudaFuncAttributeMaxDynamicSharedMemorySize,
                         ATT_SMEM_FLOATS * sizeof(float));

    dim3 mlp_grid(NROWS / 64, 3);
    mlp_kernel<<<mlp_grid, 256, MLP_SMEM_FLOATS * sizeof(float)>>>(
        KEY, QUERY, W1w, W1b, W2w, W2b, W3w, W3b,
        O1w, O1b, O2w, O2b, O3w, O3b);

    dim3 att_grid(NSEQ / 64, NB);
    attn_kernel<<<att_grid, 256, ATT_SMEM_FLOATS * sizeof(float)>>>(
        VALUE, (float*)d_out);
}